// round 1
// baseline (speedup 1.0000x reference)
#include <cuda_runtime.h>
#include <cuda_bf16.h>

// Problem dims (fixed by reference)
#define B_   2
#define S_   2048
#define D_   1024
#define E_   1024
#define H_   16
#define HD_  64
#define MTOT (B_*S_)        // 4096
#define NQKV (3*E_)         // 3072
#define BHN  (B_*H_)        // 32

// Tiling for the fp32 GEMMs
#define TBM 64
#define TBN 64
#define TBK 16

// ---- static device scratch (no allocations allowed in kernel_launch) ----
__device__ float g_q[(size_t)BHN * S_ * HD_];       // [B,H,S,HD]
__device__ float g_k[(size_t)BHN * S_ * HD_];
__device__ float g_v[(size_t)BHN * S_ * HD_];
__device__ float g_vals[(size_t)MTOT * E_];         // [B,S,E]
__device__ float g_out_scratch[(size_t)MTOT * D_];  // used only if out not in d_out
__device__ float g_attn_scratch[(size_t)BHN * S_ * S_]; // used only if attn not in d_out

// ============================================================================
// Kernel 1: QKV projection. C[m,n] = x[m,:] . w_qkv[n,:] + b_qkv[n]
// then scatter into g_q/g_k/g_v with [B,H,S,HD] layout.
// M=4096, N=3072, K=1024 (all divisible by tile dims; no bounds checks).
// ============================================================================
__global__ void qkv_kernel(const float* __restrict__ x,
                           const float* __restrict__ w,
                           const float* __restrict__ bias) {
    __shared__ float As[TBM][TBK + 1];
    __shared__ float Bs[TBN][TBK + 1];
    const int tid = threadIdx.x;
    const int tx = tid & 15, ty = tid >> 4;
    const int bm = blockIdx.y * TBM;
    const int bn = blockIdx.x * TBN;
    float acc[4][4] = {};

    for (int k0 = 0; k0 < D_; k0 += TBK) {
        #pragma unroll
        for (int i = tid; i < TBM * TBK; i += 256) {
            int r = i / TBK, c = i % TBK;
            As[r][c] = x[(size_t)(bm + r) * D_ + k0 + c];
            Bs[r][c] = w[(size_t)(bn + r) * D_ + k0 + c];
        }
        __syncthreads();
        #pragma unroll
        for (int kk = 0; kk < TBK; kk++) {
            float a[4], bv[4];
            #pragma unroll
            for (int i = 0; i < 4; i++) a[i] = As[ty * 4 + i][kk];
            #pragma unroll
            for (int j = 0; j < 4; j++) bv[j] = Bs[tx * 4 + j][kk];
            #pragma unroll
            for (int i = 0; i < 4; i++)
                #pragma unroll
                for (int j = 0; j < 4; j++)
                    acc[i][j] = fmaf(a[i], bv[j], acc[i][j]);
        }
        __syncthreads();
    }

    #pragma unroll
    for (int i = 0; i < 4; i++) {
        int m = bm + ty * 4 + i;
        int b = m / S_, s = m % S_;
        #pragma unroll
        for (int j = 0; j < 4; j++) {
            int n = bn + tx * 4 + j;
            float v = acc[i][j] + bias[n];
            int h = n / (3 * HD_);
            int r = n % (3 * HD_);
            int which = r / HD_;
            int d = r % HD_;
            size_t idx = (((size_t)b * H_ + h) * S_ + s) * HD_ + d;
            if (which == 0)      g_q[idx] = v;
            else if (which == 1) g_k[idx] = v;
            else                 g_v[idx] = v;
        }
    }
}

// ============================================================================
// Kernel 2: logits[bh, q, k] = (Q[bh,q,:] . K[bh,k,:]) / HD
// Per (b,h): M=N=2048, K=64. grid (32, 32, BHN).
// ============================================================================
__global__ void logits_kernel(float* attn_base) {
    float* attn = attn_base ? attn_base : g_attn_scratch;
    const int bh = blockIdx.z;
    const float* Q = g_q + (size_t)bh * S_ * HD_;
    const float* K = g_k + (size_t)bh * S_ * HD_;
    __shared__ float As[TBM][TBK + 1];
    __shared__ float Bs[TBN][TBK + 1];
    const int tid = threadIdx.x;
    const int tx = tid & 15, ty = tid >> 4;
    const int bm = blockIdx.y * TBM;
    const int bn = blockIdx.x * TBN;
    float acc[4][4] = {};

    for (int k0 = 0; k0 < HD_; k0 += TBK) {
        #pragma unroll
        for (int i = tid; i < TBM * TBK; i += 256) {
            int r = i / TBK, c = i % TBK;
            As[r][c] = Q[(size_t)(bm + r) * HD_ + k0 + c];
            Bs[r][c] = K[(size_t)(bn + r) * HD_ + k0 + c];
        }
        __syncthreads();
        #pragma unroll
        for (int kk = 0; kk < TBK; kk++) {
            float a[4], bv[4];
            #pragma unroll
            for (int i = 0; i < 4; i++) a[i] = As[ty * 4 + i][kk];
            #pragma unroll
            for (int j = 0; j < 4; j++) bv[j] = Bs[tx * 4 + j][kk];
            #pragma unroll
            for (int i = 0; i < 4; i++)
                #pragma unroll
                for (int j = 0; j < 4; j++)
                    acc[i][j] = fmaf(a[i], bv[j], acc[i][j]);
        }
        __syncthreads();
    }

    const float scale = 1.0f / (float)HD_;  // NOTE: reference divides by HD, not sqrt(HD)
    #pragma unroll
    for (int i = 0; i < 4; i++) {
        int m = bm + ty * 4 + i;
        #pragma unroll
        for (int j = 0; j < 4; j++) {
            int n = bn + tx * 4 + j;
            attn[(size_t)bh * S_ * S_ + (size_t)m * S_ + n] = acc[i][j] * scale;
        }
    }
}

// ============================================================================
// Kernel 3: in-place row softmax over last dim (row length S_=2048).
// One block (256 threads) per row; each thread holds 8 elements in registers.
// ============================================================================
__global__ void softmax_kernel(float* attn_base) {
    float* attn = attn_base ? attn_base : g_attn_scratch;
    float* p = attn + (size_t)blockIdx.x * S_;
    const int tid = threadIdx.x;
    __shared__ float red[256];

    float v[8];
    float lmax = -1e30f;
    #pragma unroll
    for (int i = 0; i < 8; i++) {
        v[i] = p[tid + i * 256];
        lmax = fmaxf(lmax, v[i]);
    }
    red[tid] = lmax;
    __syncthreads();
    #pragma unroll
    for (int s = 128; s > 0; s >>= 1) {
        if (tid < s) red[tid] = fmaxf(red[tid], red[tid + s]);
        __syncthreads();
    }
    const float rmax = red[0];
    __syncthreads();

    float lsum = 0.0f;
    #pragma unroll
    for (int i = 0; i < 8; i++) {
        v[i] = __expf(v[i] - rmax);
        lsum += v[i];
    }
    red[tid] = lsum;
    __syncthreads();
    #pragma unroll
    for (int s = 128; s > 0; s >>= 1) {
        if (tid < s) red[tid] += red[tid + s];
        __syncthreads();
    }
    const float inv = 1.0f / red[0];
    #pragma unroll
    for (int i = 0; i < 8; i++) p[tid + i * 256] = v[i] * inv;
}

// ============================================================================
// Kernel 4: vals[bh] = attn[bh] @ V[bh].  M=2048, N=HD=64, K=2048.
// Writes into g_vals with [B,S,E] layout (head h occupies cols h*64..h*64+63).
// grid (1, 32, BHN).
// ============================================================================
__global__ void av_kernel(const float* attn_base_in) {
    const float* attn = attn_base_in ? attn_base_in : g_attn_scratch;
    const int bh = blockIdx.z;
    const int b = bh / H_, h = bh % H_;
    const float* A = attn + (size_t)bh * S_ * S_;
    const float* V = g_v + (size_t)bh * S_ * HD_;
    __shared__ float As[TBM][TBK + 1];
    __shared__ float Bs[TBK][TBN];
    const int tid = threadIdx.x;
    const int tx = tid & 15, ty = tid >> 4;
    const int bm = blockIdx.y * TBM;
    float acc[4][4] = {};

    for (int k0 = 0; k0 < S_; k0 += TBK) {
        #pragma unroll
        for (int i = tid; i < TBM * TBK; i += 256) {
            int r = i / TBK, c = i % TBK;
            As[r][c] = A[(size_t)(bm + r) * S_ + k0 + c];
        }
        #pragma unroll
        for (int i = tid; i < TBK * TBN; i += 256) {
            int r = i / TBN, c = i % TBN;
            Bs[r][c] = V[(size_t)(k0 + r) * HD_ + c];
        }
        __syncthreads();
        #pragma unroll
        for (int kk = 0; kk < TBK; kk++) {
            float a[4], bv[4];
            #pragma unroll
            for (int i = 0; i < 4; i++) a[i] = As[ty * 4 + i][kk];
            #pragma unroll
            for (int j = 0; j < 4; j++) bv[j] = Bs[kk][tx * 4 + j];
            #pragma unroll
            for (int i = 0; i < 4; i++)
                #pragma unroll
                for (int j = 0; j < 4; j++)
                    acc[i][j] = fmaf(a[i], bv[j], acc[i][j]);
        }
        __syncthreads();
    }

    #pragma unroll
    for (int i = 0; i < 4; i++) {
        int m = bm + ty * 4 + i;
        #pragma unroll
        for (int j = 0; j < 4; j++) {
            int n = tx * 4 + j;
            g_vals[((size_t)b * S_ + m) * E_ + h * HD_ + n] = acc[i][j];
        }
    }
}

// ============================================================================
// Kernel 5: out = vals @ w_out^T + b_out.  M=4096, N=1024, K=1024.
// ============================================================================
__global__ void proj_kernel(const float* __restrict__ w,
                            const float* __restrict__ bias,
                            float* out_base) {
    float* outp = out_base ? out_base : g_out_scratch;
    __shared__ float As[TBM][TBK + 1];
    __shared__ float Bs[TBN][TBK + 1];
    const int tid = threadIdx.x;
    const int tx = tid & 15, ty = tid >> 4;
    const int bm = blockIdx.y * TBM;
    const int bn = blockIdx.x * TBN;
    float acc[4][4] = {};

    for (int k0 = 0; k0 < E_; k0 += TBK) {
        #pragma unroll
        for (int i = tid; i < TBM * TBK; i += 256) {
            int r = i / TBK, c = i % TBK;
            As[r][c] = g_vals[(size_t)(bm + r) * E_ + k0 + c];
            Bs[r][c] = w[(size_t)(bn + r) * E_ + k0 + c];
        }
        __syncthreads();
        #pragma unroll
        for (int kk = 0; kk < TBK; kk++) {
            float a[4], bv[4];
            #pragma unroll
            for (int i = 0; i < 4; i++) a[i] = As[ty * 4 + i][kk];
            #pragma unroll
            for (int j = 0; j < 4; j++) bv[j] = Bs[tx * 4 + j][kk];
            #pragma unroll
            for (int i = 0; i < 4; i++)
                #pragma unroll
                for (int j = 0; j < 4; j++)
                    acc[i][j] = fmaf(a[i], bv[j], acc[i][j]);
        }
        __syncthreads();
    }

    #pragma unroll
    for (int i = 0; i < 4; i++) {
        int m = bm + ty * 4 + i;
        #pragma unroll
        for (int j = 0; j < 4; j++) {
            int n = bn + tx * 4 + j;
            outp[(size_t)m * D_ + n] = acc[i][j] + bias[n];
        }
    }
}

// ============================================================================
// Launch. Inputs (metadata order): x, w_qkv, b_qkv, w_out, b_out.
// Output layout assumed: flatten of (out [B,S,D], attn [B,H,S,S]); handles
// out-only / attn-only sizes too via scratch fallbacks.
// ============================================================================
extern "C" void kernel_launch(void* const* d_in, const int* in_sizes, int n_in,
                              void* d_out, int out_size) {
    const float* x     = (const float*)d_in[0];
    const float* w_qkv = (const float*)d_in[1];
    const float* b_qkv = (const float*)d_in[2];
    const float* w_out = (const float*)d_in[3];
    const float* b_out = (const float*)d_in[4];
    float* dout = (float*)d_out;

    const long long OUTN  = (long long)MTOT * D_;          // 4,194,304
    const long long ATTNN = (long long)BHN * S_ * S_;      // 134,217,728
    float* out_ext  = nullptr;  // null -> device scratch
    float* attn_ext = nullptr;
    const long long osz = (long long)out_size;
    if (osz >= OUTN + ATTNN) { out_ext = dout; attn_ext = dout + OUTN; }
    else if (osz == ATTNN)   { attn_ext = dout; }
    else                     { out_ext = dout; }

    dim3 t(256);
    qkv_kernel    <<<dim3(NQKV / TBN, MTOT / TBM), t>>>(x, w_qkv, b_qkv);
    logits_kernel <<<dim3(S_ / TBN, S_ / TBM, BHN), t>>>(attn_ext);
    softmax_kernel<<<BHN * S_, 256>>>(attn_ext);
    av_kernel     <<<dim3(1, S_ / TBM, BHN), t>>>(attn_ext);
    proj_kernel   <<<dim3(D_ / TBN, MTOT / TBM), t>>>(w_out, b_out, out_ext);
}

// round 2
// speedup vs baseline: 2.8884x; 2.8884x over previous
#include <cuda_runtime.h>
#include <cuda_bf16.h>
#include <cstdint>

// Problem dims (fixed by reference)
#define B_   2
#define S_   2048
#define D_   1024
#define E_   1024
#define H_   16
#define HD_  64
#define MTOT (B_*S_)        // 4096
#define NQKV (3*E_)         // 3072
#define BHN  (B_*H_)        // 32

// ---- static device scratch (no allocations allowed) ----
__device__ float g_q[(size_t)BHN * S_ * HD_];       // [B,H,S,HD]
__device__ float g_k[(size_t)BHN * S_ * HD_];
__device__ float g_v[(size_t)BHN * S_ * HD_];
__device__ float g_vals[(size_t)MTOT * E_];         // [B,S,E]
__device__ float g_out_scratch[(size_t)MTOT * D_];
__device__ float g_attn_scratch[(size_t)BHN * S_ * S_];

__device__ __forceinline__ uint32_t f2tf32(float x) {
    uint32_t u;
    asm("cvt.rna.tf32.f32 %0, %1;" : "=r"(u) : "f"(x));
    return u;
}

__device__ __forceinline__ void mma_tf32(float c[4], const uint32_t a[4], const uint32_t b[2]) {
    asm volatile(
        "mma.sync.aligned.m16n8k8.row.col.f32.tf32.tf32.f32 "
        "{%0,%1,%2,%3}, {%4,%5,%6,%7}, {%8,%9}, {%0,%1,%2,%3};\n"
        : "+f"(c[0]), "+f"(c[1]), "+f"(c[2]), "+f"(c[3])
        : "r"(a[0]), "r"(a[1]), "r"(a[2]), "r"(a[3]), "r"(b[0]), "r"(b[1]));
}

// ============================================================================
// One templated tensor-core GEMM. All are "NT" style after smem staging:
// C[m,n] = sum_k A[m,k] * Bmat[n,k]
// MODE 0: qkv   — A=x[4096,1024], B=w_qkv[3072,1024], epilogue: +bias, scatter q/k/v
// MODE 1: logits— per bh: A=Q[2048,64], B=K[2048,64], epilogue: *1/64 -> attn
// MODE 2: av    — per bh: A=attn[2048,2048], B=V[2048,64] (transposed in smem) -> g_vals
// MODE 3: proj  — A=g_vals[4096,1024], B=w_out[1024,1024], +bias -> out
// ============================================================================
template<int MODE>
__global__ __launch_bounds__(256)
void mma_gemm(const float* __restrict__ p0, const float* __restrict__ p1,
              const float* __restrict__ bias, float* __restrict__ pC) {
    constexpr int BM = 128;
    constexpr int BN = (MODE == 2) ? 64 : 128;
    constexpr int BK = 16;
    constexpr int KDIM = (MODE == 1) ? 64 : ((MODE == 2) ? 2048 : 1024);
    constexpr int KT = KDIM / BK;
    constexpr int WGM = (MODE == 2) ? 4 : 2;   // warp grid
    constexpr int WGN = (MODE == 2) ? 2 : 4;
    constexpr int WM = BM / WGM;               // warp tile
    constexpr int WN = BN / WGN;
    constexpr int MT = WM / 16;
    constexpr int NTL = WN / 8;
    constexpr int SAS = BK + 4;                // 20-word row stride (conflict-free frag reads)
    constexpr int NREP_A = (BM * BK) / (4 * 256);  // 2
    constexpr int NREP_B = (BN * BK) / (4 * 256);  // 2 (or 1 for MODE 2)

    __shared__ uint32_t As[2][BM * SAS];
    __shared__ uint32_t Bs[2][BN * SAS];

    const int tid  = threadIdx.x;
    const int wid  = tid >> 5;
    const int lane = tid & 31;
    const int g    = lane >> 2;   // group id (row within tile)
    const int tg   = lane & 3;    // thread-in-group (k / col pairs)
    const int warpM = wid / WGN;
    const int warpN = wid % WGN;
    const int bm = blockIdx.y * BM;
    const int bn = blockIdx.x * BN;
    const int bh = blockIdx.z;

    // Resolve operand pointers per mode
    const float* gA;
    const float* gB;
    if (MODE == 0)      { gA = p0; gB = p1; }
    else if (MODE == 1) { gA = g_q + (size_t)bh * S_ * HD_;
                          gB = g_k + (size_t)bh * S_ * HD_; }
    else if (MODE == 2) { const float* attn = p0 ? p0 : g_attn_scratch;
                          gA = attn + (size_t)bh * S_ * S_;
                          gB = g_v + (size_t)bh * S_ * HD_; }
    else                { gA = g_vals; gB = p1; }

    float4 pA[NREP_A];
    float4 pB[(NREP_B > 0) ? NREP_B : 1];

    auto loadA = [&](int kt) {
        #pragma unroll
        for (int rep = 0; rep < NREP_A; rep++) {
            int idx = rep * 256 + tid;
            int row = idx >> 2, c4 = idx & 3;
            pA[rep] = *reinterpret_cast<const float4*>(
                gA + (size_t)(bm + row) * KDIM + kt * BK + c4 * 4);
        }
    };
    auto storeA = [&](int buf) {
        #pragma unroll
        for (int rep = 0; rep < NREP_A; rep++) {
            int idx = rep * 256 + tid;
            int row = idx >> 2, c4 = idx & 3;
            uint32_t* d = &As[buf][row * SAS + c4 * 4];
            d[0] = f2tf32(pA[rep].x); d[1] = f2tf32(pA[rep].y);
            d[2] = f2tf32(pA[rep].z); d[3] = f2tf32(pA[rep].w);
        }
    };
    auto loadB = [&](int kt) {
        if (MODE == 2) {
            // V[k][n] (64 cols). lane: k = tid&15, n-quad = tid>>4
            int k = tid & 15, nq = tid >> 4;
            pB[0] = *reinterpret_cast<const float4*>(gB + (size_t)(kt * BK + k) * HD_ + nq * 4);
        } else {
            #pragma unroll
            for (int rep = 0; rep < NREP_B; rep++) {
                int idx = rep * 256 + tid;
                int row = idx >> 2, c4 = idx & 3;
                pB[rep] = *reinterpret_cast<const float4*>(
                    gB + (size_t)(bn + row) * KDIM + kt * BK + c4 * 4);
            }
        }
    };
    auto storeB = [&](int buf) {
        if (MODE == 2) {
            int k = tid & 15, nq = tid >> 4;
            // transpose to Bs[n][k]
            Bs[buf][(nq * 4 + 0) * SAS + k] = f2tf32(pB[0].x);
            Bs[buf][(nq * 4 + 1) * SAS + k] = f2tf32(pB[0].y);
            Bs[buf][(nq * 4 + 2) * SAS + k] = f2tf32(pB[0].z);
            Bs[buf][(nq * 4 + 3) * SAS + k] = f2tf32(pB[0].w);
        } else {
            #pragma unroll
            for (int rep = 0; rep < NREP_B; rep++) {
                int idx = rep * 256 + tid;
                int row = idx >> 2, c4 = idx & 3;
                uint32_t* d = &Bs[buf][row * SAS + c4 * 4];
                d[0] = f2tf32(pB[rep].x); d[1] = f2tf32(pB[rep].y);
                d[2] = f2tf32(pB[rep].z); d[3] = f2tf32(pB[rep].w);
            }
        }
    };

    float acc[MT][NTL][4];
    #pragma unroll
    for (int i = 0; i < MT; i++)
        #pragma unroll
        for (int j = 0; j < NTL; j++)
            #pragma unroll
            for (int e = 0; e < 4; e++) acc[i][j][e] = 0.0f;

    loadA(0); loadB(0);
    storeA(0); storeB(0);
    __syncthreads();

    int buf = 0;
    #pragma unroll 1
    for (int kt = 0; kt < KT; kt++) {
        if (kt + 1 < KT) { loadA(kt + 1); loadB(kt + 1); }

        #pragma unroll
        for (int ks = 0; ks < 2; ks++) {
            const int kb = ks * 8;
            uint32_t af[MT][4], bfr[NTL][2];
            #pragma unroll
            for (int i = 0; i < MT; i++) {
                const int rm = warpM * WM + i * 16;
                af[i][0] = As[buf][(rm + g)     * SAS + kb + tg];
                af[i][1] = As[buf][(rm + g + 8) * SAS + kb + tg];
                af[i][2] = As[buf][(rm + g)     * SAS + kb + tg + 4];
                af[i][3] = As[buf][(rm + g + 8) * SAS + kb + tg + 4];
            }
            #pragma unroll
            for (int j = 0; j < NTL; j++) {
                const int cn = warpN * WN + j * 8;
                bfr[j][0] = Bs[buf][(cn + g) * SAS + kb + tg];
                bfr[j][1] = Bs[buf][(cn + g) * SAS + kb + tg + 4];
            }
            #pragma unroll
            for (int i = 0; i < MT; i++)
                #pragma unroll
                for (int j = 0; j < NTL; j++)
                    mma_tf32(acc[i][j], af[i], bfr[j]);
        }

        if (kt + 1 < KT) {
            storeA(buf ^ 1); storeB(buf ^ 1);
            __syncthreads();
            buf ^= 1;
        }
    }

    // ---- Epilogues ----
    #pragma unroll
    for (int i = 0; i < MT; i++) {
        const int rm = bm + warpM * WM + i * 16;
        const int r0 = rm + g;
        const int r1 = rm + g + 8;
        #pragma unroll
        for (int j = 0; j < NTL; j++) {
            const int n0 = bn + warpN * WN + j * 8;  // 8-aligned
            const int nc = n0 + 2 * tg;
            float c0 = acc[i][j][0], c1 = acc[i][j][1];
            float c2 = acc[i][j][2], c3 = acc[i][j][3];

            if (MODE == 0) {
                const float b0 = bias[nc], b1 = bias[nc + 1];
                const int h = n0 / (3 * HD_);
                const int which = (n0 % (3 * HD_)) / HD_;
                const int d = (n0 % HD_) + 2 * tg;
                float* dst = (which == 0) ? g_q : (which == 1) ? g_k : g_v;
                const int bb0 = r0 >> 11, ss0 = r0 & (S_ - 1);
                const int bb1 = r1 >> 11, ss1 = r1 & (S_ - 1);
                float2 v0 = make_float2(c0 + b0, c1 + b1);
                float2 v1 = make_float2(c2 + b0, c3 + b1);
                *reinterpret_cast<float2*>(dst + ((((size_t)bb0 * H_ + h) * S_ + ss0) * HD_ + d)) = v0;
                *reinterpret_cast<float2*>(dst + ((((size_t)bb1 * H_ + h) * S_ + ss1) * HD_ + d)) = v1;
            } else if (MODE == 1) {
                float* attn = pC ? pC : g_attn_scratch;
                const float sc = 1.0f / (float)HD_;
                float* base = attn + (size_t)bh * S_ * S_;
                *reinterpret_cast<float2*>(base + (size_t)r0 * S_ + nc) = make_float2(c0 * sc, c1 * sc);
                *reinterpret_cast<float2*>(base + (size_t)r1 * S_ + nc) = make_float2(c2 * sc, c3 * sc);
            } else if (MODE == 2) {
                const int bb = bh >> 4, h = bh & 15;
                float* base = g_vals + (size_t)bb * S_ * E_ + (size_t)h * HD_;
                *reinterpret_cast<float2*>(base + (size_t)r0 * E_ + nc) = make_float2(c0, c1);
                *reinterpret_cast<float2*>(base + (size_t)r1 * E_ + nc) = make_float2(c2, c3);
            } else {
                float* outp = pC ? pC : g_out_scratch;
                const float b0 = bias[nc], b1 = bias[nc + 1];
                *reinterpret_cast<float2*>(outp + (size_t)r0 * D_ + nc) = make_float2(c0 + b0, c1 + b1);
                *reinterpret_cast<float2*>(outp + (size_t)r1 * D_ + nc) = make_float2(c2 + b0, c3 + b1);
            }
        }
    }
}

// ============================================================================
// Row softmax over last dim (row length 2048), in place.
// ============================================================================
__global__ void softmax_kernel(float* attn_base) {
    float* attn = attn_base ? attn_base : g_attn_scratch;
    float* p = attn + (size_t)blockIdx.x * S_;
    const int tid = threadIdx.x;
    __shared__ float red[256];

    float v[8];
    float lmax = -1e30f;
    #pragma unroll
    for (int i = 0; i < 8; i++) {
        v[i] = p[tid + i * 256];
        lmax = fmaxf(lmax, v[i]);
    }
    red[tid] = lmax;
    __syncthreads();
    #pragma unroll
    for (int s = 128; s > 0; s >>= 1) {
        if (tid < s) red[tid] = fmaxf(red[tid], red[tid + s]);
        __syncthreads();
    }
    const float rmax = red[0];
    __syncthreads();

    float lsum = 0.0f;
    #pragma unroll
    for (int i = 0; i < 8; i++) {
        v[i] = __expf(v[i] - rmax);
        lsum += v[i];
    }
    red[tid] = lsum;
    __syncthreads();
    #pragma unroll
    for (int s = 128; s > 0; s >>= 1) {
        if (tid < s) red[tid] += red[tid + s];
        __syncthreads();
    }
    const float inv = 1.0f / red[0];
    #pragma unroll
    for (int i = 0; i < 8; i++) p[tid + i * 256] = v[i] * inv;
}

// ============================================================================
// Launch. Inputs: x, w_qkv, b_qkv, w_out, b_out.
// Output: flatten of (out [B,S,D], attn [B,H,S,S]); handles partial cases.
// ============================================================================
extern "C" void kernel_launch(void* const* d_in, const int* in_sizes, int n_in,
                              void* d_out, int out_size) {
    const float* x     = (const float*)d_in[0];
    const float* w_qkv = (const float*)d_in[1];
    const float* b_qkv = (const float*)d_in[2];
    const float* w_out = (const float*)d_in[3];
    const float* b_out = (const float*)d_in[4];
    float* dout = (float*)d_out;

    const long long OUTN  = (long long)MTOT * D_;
    const long long ATTNN = (long long)BHN * S_ * S_;
    float* out_ext  = nullptr;
    float* attn_ext = nullptr;
    const long long osz = (long long)out_size;
    if (osz >= OUTN + ATTNN) { out_ext = dout; attn_ext = dout + OUTN; }
    else if (osz == ATTNN)   { attn_ext = dout; }
    else                     { out_ext = dout; }

    dim3 t(256);
    mma_gemm<0><<<dim3(NQKV / 128, MTOT / 128), t>>>(x, w_qkv, b_qkv, nullptr);
    mma_gemm<1><<<dim3(S_ / 128, S_ / 128, BHN), t>>>(nullptr, nullptr, nullptr, attn_ext);
    softmax_kernel<<<BHN * S_, 256>>>(attn_ext);
    mma_gemm<2><<<dim3(1, S_ / 128, BHN), t>>>(attn_ext, nullptr, nullptr, nullptr);
    mma_gemm<3><<<dim3(D_ / 128, MTOT / 128), t>>>(nullptr, w_out, b_out, out_ext);
}

// round 3
// speedup vs baseline: 3.5647x; 1.2341x over previous
#include <cuda_runtime.h>
#include <cuda_bf16.h>
#include <cstdint>

// Problem dims (fixed by reference)
#define B_   2
#define S_   2048
#define D_   1024
#define E_   1024
#define H_   16
#define HD_  64
#define MTOT (B_*S_)        // 4096
#define NQKV (3*E_)         // 3072
#define BHN  (B_*H_)        // 32

// ---- static device scratch (no allocations allowed) ----
__device__ __align__(256) float g_q[(size_t)BHN * S_ * HD_];       // [B,H,S,HD], tf32-rounded
__device__ __align__(256) float g_k[(size_t)BHN * S_ * HD_];
__device__ __align__(256) float g_v[(size_t)BHN * S_ * HD_];
__device__ __align__(256) float g_vals[(size_t)MTOT * E_];         // [B,S,E]
__device__ __align__(256) float g_out_scratch[(size_t)MTOT * D_];
__device__ __align__(256) float g_attn_scratch[(size_t)BHN * S_ * S_];

__device__ __forceinline__ uint32_t f2tf32(float x) {
    uint32_t u;
    asm("cvt.rna.tf32.f32 %0, %1;" : "=r"(u) : "f"(x));
    return u;
}

__device__ __forceinline__ void mma_tf32(float c[4], const uint32_t a[4], const uint32_t b[2]) {
    asm volatile(
        "mma.sync.aligned.m16n8k8.row.col.f32.tf32.tf32.f32 "
        "{%0,%1,%2,%3}, {%4,%5,%6,%7}, {%8,%9}, {%0,%1,%2,%3};\n"
        : "+f"(c[0]), "+f"(c[1]), "+f"(c[2]), "+f"(c[3])
        : "r"(a[0]), "r"(a[1]), "r"(a[2]), "r"(a[3]), "r"(b[0]), "r"(b[1]));
}

__device__ __forceinline__ void cpa16(void* s, const void* g) {
    uint32_t sa = (uint32_t)__cvta_generic_to_shared(s);
    asm volatile("cp.async.cg.shared.global [%0], [%1], 16;" :: "r"(sa), "l"(g));
}
#define CP_COMMIT asm volatile("cp.async.commit_group;")
#define CP_WAIT0  asm volatile("cp.async.wait_group 0;")

// ============================================================================
// Dense GEMMs (QKV projection / output projection), tf32 tensor cores.
// MODE 0: qkv — A=x[4096,1024], B=w_qkv[3072,1024]; +bias, scatter q/k/v (tf32-rounded)
// MODE 3: proj — A=g_vals[4096,1024], B=w_out[1024,1024]; +bias -> out
// ============================================================================
template<int MODE>
__global__ __launch_bounds__(256)
void mma_gemm(const float* __restrict__ p0, const float* __restrict__ p1,
              const float* __restrict__ bias, float* __restrict__ pC) {
    constexpr int BM = 128, BN = 128, BK = 16;
    constexpr int KDIM = 1024;
    constexpr int KT = KDIM / BK;
    constexpr int SAS = BK + 4;

    __shared__ uint32_t As[2][BM * SAS];
    __shared__ uint32_t Bs[2][BN * SAS];

    const int tid = threadIdx.x;
    const int wid = tid >> 5, lane = tid & 31;
    const int g = lane >> 2, tg = lane & 3;
    const int warpM = wid / 4, warpN = wid % 4;   // 2x4 warp grid, warp tile 64x32
    const int bm = blockIdx.y * BM;
    const int bn = blockIdx.x * BN;

    const float* gA = (MODE == 0) ? p0 : g_vals;
    const float* gB = p1;

    float4 pA[2], pB[2];
    auto loadA = [&](int kt) {
        #pragma unroll
        for (int rep = 0; rep < 2; rep++) {
            int idx = rep * 256 + tid, row = idx >> 2, c4 = idx & 3;
            pA[rep] = *reinterpret_cast<const float4*>(gA + (size_t)(bm + row) * KDIM + kt * BK + c4 * 4);
        }
    };
    auto storeA = [&](int buf) {
        #pragma unroll
        for (int rep = 0; rep < 2; rep++) {
            int idx = rep * 256 + tid, row = idx >> 2, c4 = idx & 3;
            uint32_t* d = &As[buf][row * SAS + c4 * 4];
            d[0] = f2tf32(pA[rep].x); d[1] = f2tf32(pA[rep].y);
            d[2] = f2tf32(pA[rep].z); d[3] = f2tf32(pA[rep].w);
        }
    };
    auto loadB = [&](int kt) {
        #pragma unroll
        for (int rep = 0; rep < 2; rep++) {
            int idx = rep * 256 + tid, row = idx >> 2, c4 = idx & 3;
            pB[rep] = *reinterpret_cast<const float4*>(gB + (size_t)(bn + row) * KDIM + kt * BK + c4 * 4);
        }
    };
    auto storeB = [&](int buf) {
        #pragma unroll
        for (int rep = 0; rep < 2; rep++) {
            int idx = rep * 256 + tid, row = idx >> 2, c4 = idx & 3;
            uint32_t* d = &Bs[buf][row * SAS + c4 * 4];
            d[0] = f2tf32(pB[rep].x); d[1] = f2tf32(pB[rep].y);
            d[2] = f2tf32(pB[rep].z); d[3] = f2tf32(pB[rep].w);
        }
    };

    float acc[4][4][4] = {};
    loadA(0); loadB(0); storeA(0); storeB(0);
    __syncthreads();

    int buf = 0;
    #pragma unroll 1
    for (int kt = 0; kt < KT; kt++) {
        if (kt + 1 < KT) { loadA(kt + 1); loadB(kt + 1); }
        #pragma unroll
        for (int ks = 0; ks < 2; ks++) {
            const int kb = ks * 8;
            uint32_t af[4][4], bfr[4][2];
            #pragma unroll
            for (int i = 0; i < 4; i++) {
                const int rm = warpM * 64 + i * 16;
                af[i][0] = As[buf][(rm + g) * SAS + kb + tg];
                af[i][1] = As[buf][(rm + g + 8) * SAS + kb + tg];
                af[i][2] = As[buf][(rm + g) * SAS + kb + tg + 4];
                af[i][3] = As[buf][(rm + g + 8) * SAS + kb + tg + 4];
            }
            #pragma unroll
            for (int j = 0; j < 4; j++) {
                const int cn = warpN * 32 + j * 8;
                bfr[j][0] = Bs[buf][(cn + g) * SAS + kb + tg];
                bfr[j][1] = Bs[buf][(cn + g) * SAS + kb + tg + 4];
            }
            #pragma unroll
            for (int i = 0; i < 4; i++)
                #pragma unroll
                for (int j = 0; j < 4; j++)
                    mma_tf32(acc[i][j], af[i], bfr[j]);
        }
        if (kt + 1 < KT) {
            storeA(buf ^ 1); storeB(buf ^ 1);
            __syncthreads();
            buf ^= 1;
        }
    }

    #pragma unroll
    for (int i = 0; i < 4; i++) {
        const int rm = bm + warpM * 64 + i * 16;
        const int r0 = rm + g, r1 = rm + g + 8;
        #pragma unroll
        for (int j = 0; j < 4; j++) {
            const int n0 = bn + warpN * 32 + j * 8;
            const int nc = n0 + 2 * tg;
            float c0 = acc[i][j][0], c1 = acc[i][j][1];
            float c2 = acc[i][j][2], c3 = acc[i][j][3];
            if (MODE == 0) {
                const float b0 = bias[nc], b1 = bias[nc + 1];
                const int h = n0 / (3 * HD_);
                const int which = (n0 % (3 * HD_)) / HD_;
                const int d = (n0 % HD_) + 2 * tg;
                float* dst = (which == 0) ? g_q : (which == 1) ? g_k : g_v;
                const int bb0 = r0 >> 11, ss0 = r0 & (S_ - 1);
                const int bb1 = r1 >> 11, ss1 = r1 & (S_ - 1);
                // store tf32-rounded so the fused kernel can cp.async raw bits
                float2 v0 = make_float2(__uint_as_float(f2tf32(c0 + b0)), __uint_as_float(f2tf32(c1 + b1)));
                float2 v1 = make_float2(__uint_as_float(f2tf32(c2 + b0)), __uint_as_float(f2tf32(c3 + b1)));
                *reinterpret_cast<float2*>(dst + ((((size_t)bb0 * H_ + h) * S_ + ss0) * HD_ + d)) = v0;
                *reinterpret_cast<float2*>(dst + ((((size_t)bb1 * H_ + h) * S_ + ss1) * HD_ + d)) = v1;
            } else {
                float* outp = pC ? pC : g_out_scratch;
                const float b0 = bias[nc], b1 = bias[nc + 1];
                *reinterpret_cast<float2*>(outp + (size_t)r0 * D_ + nc) = make_float2(c0 + b0, c1 + b1);
                *reinterpret_cast<float2*>(outp + (size_t)r1 * D_ + nc) = make_float2(c2 + b0, c3 + b1);
            }
        }
    }
}

// ============================================================================
// Fused attention: logits + exact softmax + AV, attn matrix written once.
// Block = (128 q-rows, one bh). 256 threads / 8 warps (2x4 grid).
// Pass 1: l[row] = sum_k exp(q.k/64)    (K streamed, double-buffered cp.async)
// Pass 2: recompute S, p = exp(s/64)/l, write attn, O += P@V (tensor cores)
// Smem: Qs[128][68], Xs[2][128][76] (K/V ring), Ps[128][132], Lrow[128]
// ============================================================================
#define QSTR 68
#define XSTR 76
#define PSTR 132
#define FA_SMEM ((128*QSTR + 2*128*XSTR + 128*PSTR) * 4 + 128 * 4)

__global__ __launch_bounds__(256)
void fused_attn(float* __restrict__ attn_ext) {
    extern __shared__ uint32_t sm[];
    uint32_t* Qs = sm;                       // 128*68
    uint32_t* Xs = Qs + 128 * QSTR;          // 2 * 128*76
    uint32_t* Ps = Xs + 2 * 128 * XSTR;      // 128*132
    float* Lrow  = (float*)(Ps + 128 * PSTR);

    const int tid = threadIdx.x;
    const int wid = tid >> 5, lane = tid & 31;
    const int g = lane >> 2, tg = lane & 3;
    const int warpM = wid >> 2, warpN = wid & 3;   // 2x4
    const int wm = warpM * 64;
    const int bm = blockIdx.x * 128;               // q-row block
    const int bh = blockIdx.y;
    const float sc = 1.0f / (float)HD_;

    const float* gQ = g_q + (size_t)bh * S_ * HD_ + (size_t)bm * HD_;
    const float* gK = g_k + (size_t)bh * S_ * HD_;
    const float* gV = g_v + (size_t)bh * S_ * HD_;
    float* attnp = (attn_ext ? attn_ext : g_attn_scratch) + (size_t)bh * S_ * S_;

    // ---- async tile loaders (128 rows x 64 cols) ----
    auto load_q = [&]() {
        #pragma unroll
        for (int rep = 0; rep < 8; rep++) {
            int idx = rep * 256 + tid, row = idx >> 4, q4 = idx & 15;
            cpa16(&Qs[row * QSTR + q4 * 4], gQ + row * HD_ + q4 * 4);
        }
    };
    auto load_kv = [&](const float* src, int kt, int b) {
        const float* base = src + (size_t)kt * 128 * HD_;
        #pragma unroll
        for (int rep = 0; rep < 8; rep++) {
            int idx = rep * 256 + tid, row = idx >> 4, q4 = idx & 15;
            cpa16(&Xs[b * 128 * XSTR + row * XSTR + q4 * 4], base + row * HD_ + q4 * 4);
        }
    };

    // ---- S = Q @ K^T tile compute (128x128), K in Xs[b] ----
    auto compute_S = [&](int b, float acc[4][4][4]) {
        #pragma unroll
        for (int i = 0; i < 4; i++)
            #pragma unroll
            for (int j = 0; j < 4; j++)
                #pragma unroll
                for (int e = 0; e < 4; e++) acc[i][j][e] = 0.0f;
        const uint32_t* Kb = Xs + b * 128 * XSTR;
        #pragma unroll
        for (int ks = 0; ks < 8; ks++) {
            const int kb = ks * 8;
            uint32_t af[4][4], bfr[4][2];
            #pragma unroll
            for (int i = 0; i < 4; i++) {
                const int r = wm + i * 16 + g;
                af[i][0] = Qs[r * QSTR + kb + tg];
                af[i][1] = Qs[(r + 8) * QSTR + kb + tg];
                af[i][2] = Qs[r * QSTR + kb + tg + 4];
                af[i][3] = Qs[(r + 8) * QSTR + kb + tg + 4];
            }
            #pragma unroll
            for (int j = 0; j < 4; j++) {
                const int c = warpN * 32 + j * 8 + g;
                bfr[j][0] = Kb[c * XSTR + kb + tg];
                bfr[j][1] = Kb[c * XSTR + kb + tg + 4];
            }
            #pragma unroll
            for (int i = 0; i < 4; i++)
                #pragma unroll
                for (int j = 0; j < 4; j++)
                    mma_tf32(acc[i][j], af[i], bfr[j]);
        }
    };

    // ---- prologue ----
    if (tid < 128) Lrow[tid] = 0.0f;
    load_q();
    load_kv(gK, 0, 0);
    CP_COMMIT;
    CP_WAIT0;
    __syncthreads();

    // ================= pass 1: row sums of exp =================
    float lp[4][2] = {};
    int a = 0;
    #pragma unroll 1
    for (int kt = 0; kt < 16; kt++) {
        if (kt < 15) { load_kv(gK, kt + 1, a ^ 1); CP_COMMIT; }
        float acc[4][4][4];
        compute_S(a, acc);
        #pragma unroll
        for (int i = 0; i < 4; i++)
            #pragma unroll
            for (int j = 0; j < 4; j++) {
                lp[i][0] += __expf(acc[i][j][0] * sc) + __expf(acc[i][j][1] * sc);
                lp[i][1] += __expf(acc[i][j][2] * sc) + __expf(acc[i][j][3] * sc);
            }
        if (kt < 15) { CP_WAIT0; __syncthreads(); a ^= 1; }
    }
    // reduce across tg (shfl) then across warpN (smem atomics)
    #pragma unroll
    for (int i = 0; i < 4; i++)
        #pragma unroll
        for (int h = 0; h < 2; h++) {
            float v = lp[i][h];
            v += __shfl_xor_sync(0xffffffff, v, 1);
            v += __shfl_xor_sync(0xffffffff, v, 2);
            if (tg == 0) atomicAdd(&Lrow[wm + i * 16 + h * 8 + g], v);
        }
    __syncthreads();
    if (tid < 128) Lrow[tid] = 1.0f / Lrow[tid];

    // reload K[0] for pass 2 (into the free buffer)
    load_kv(gK, 0, a ^ 1);
    CP_COMMIT;
    CP_WAIT0;
    a ^= 1;
    __syncthreads();   // Lrow inverse + K[0] visible

    // ================= pass 2: attn write + O accumulation =================
    float oacc[4][2][4] = {};
    #pragma unroll 1
    for (int kt = 0; kt < 16; kt++) {
        if (kt < 15) { load_kv(gK, kt + 1, a ^ 1); CP_COMMIT; }
        float acc[4][4][4];
        compute_S(a, acc);
        __syncthreads();                       // all warps done reading K in Xs[a]
        load_kv(gV, kt, a); CP_COMMIT;         // V[kt] overwrites K[kt]; overlaps below

        // exp, normalize, write attn, stage P (tf32)
        #pragma unroll
        for (int i = 0; i < 4; i++) {
            const int r0 = wm + i * 16 + g, r1 = r0 + 8;
            const float li0 = Lrow[r0], li1 = Lrow[r1];
            #pragma unroll
            for (int j = 0; j < 4; j++) {
                const int col = warpN * 32 + j * 8 + 2 * tg;
                float p0 = __expf(acc[i][j][0] * sc) * li0;
                float p1 = __expf(acc[i][j][1] * sc) * li0;
                float p2 = __expf(acc[i][j][2] * sc) * li1;
                float p3 = __expf(acc[i][j][3] * sc) * li1;
                *reinterpret_cast<float2*>(attnp + (size_t)(bm + r0) * S_ + kt * 128 + col) = make_float2(p0, p1);
                *reinterpret_cast<float2*>(attnp + (size_t)(bm + r1) * S_ + kt * 128 + col) = make_float2(p2, p3);
                Ps[r0 * PSTR + warpN * 32 + j * 8 + 2 * tg]     = f2tf32(p0);
                Ps[r0 * PSTR + warpN * 32 + j * 8 + 2 * tg + 1] = f2tf32(p1);
                Ps[r1 * PSTR + warpN * 32 + j * 8 + 2 * tg]     = f2tf32(p2);
                Ps[r1 * PSTR + warpN * 32 + j * 8 + 2 * tg + 1] = f2tf32(p3);
            }
        }
        CP_WAIT0;          // V[kt] (and K[kt+1]) landed
        __syncthreads();   // Ps + V visible to all

        // O += P @ V  (P: [128m][128k] in Ps, V: [128k][64n] in Xs[a])
        const uint32_t* Vb = Xs + a * 128 * XSTR;
        #pragma unroll
        for (int k8 = 0; k8 < 16; k8++) {
            const int kb = k8 * 8;
            uint32_t af[4][4], bfr[2][2];
            #pragma unroll
            for (int i = 0; i < 4; i++) {
                const int r = wm + i * 16 + g;
                af[i][0] = Ps[r * PSTR + kb + tg];
                af[i][1] = Ps[(r + 8) * PSTR + kb + tg];
                af[i][2] = Ps[r * PSTR + kb + tg + 4];
                af[i][3] = Ps[(r + 8) * PSTR + kb + tg + 4];
            }
            #pragma unroll
            for (int j = 0; j < 2; j++) {
                const int cn = warpN * 16 + j * 8 + g;
                bfr[j][0] = Vb[(kb + tg) * XSTR + cn];
                bfr[j][1] = Vb[(kb + tg + 4) * XSTR + cn];
            }
            #pragma unroll
            for (int i = 0; i < 4; i++)
                #pragma unroll
                for (int j = 0; j < 2; j++)
                    mma_tf32(oacc[i][j], af[i], bfr[j]);
        }
        if (kt < 15) {
            __syncthreads();   // AV done reading Xs[a] before next K load reuses it
            a ^= 1;
        }
    }

    // ---- epilogue: O (128x64) -> g_vals[b][s][h*64 + n] ----
    const int bb = bh >> 4, h = bh & 15;
    float* vbase = g_vals + (size_t)bb * S_ * E_ + (size_t)h * HD_;
    #pragma unroll
    for (int i = 0; i < 4; i++) {
        const int r0 = bm + wm + i * 16 + g, r1 = r0 + 8;
        #pragma unroll
        for (int j = 0; j < 2; j++) {
            const int cn = warpN * 16 + j * 8 + 2 * tg;
            *reinterpret_cast<float2*>(vbase + (size_t)r0 * E_ + cn) = make_float2(oacc[i][j][0], oacc[i][j][1]);
            *reinterpret_cast<float2*>(vbase + (size_t)r1 * E_ + cn) = make_float2(oacc[i][j][2], oacc[i][j][3]);
        }
    }
}

// ============================================================================
// Launch. Inputs: x, w_qkv, b_qkv, w_out, b_out.
// Output: flatten of (out [B,S,D], attn [B,H,S,S]); handles partial cases.
// ============================================================================
extern "C" void kernel_launch(void* const* d_in, const int* in_sizes, int n_in,
                              void* d_out, int out_size) {
    const float* x     = (const float*)d_in[0];
    const float* w_qkv = (const float*)d_in[1];
    const float* b_qkv = (const float*)d_in[2];
    const float* w_out = (const float*)d_in[3];
    const float* b_out = (const float*)d_in[4];
    float* dout = (float*)d_out;

    const long long OUTN  = (long long)MTOT * D_;
    const long long ATTNN = (long long)BHN * S_ * S_;
    float* out_ext  = nullptr;
    float* attn_ext = nullptr;
    const long long osz = (long long)out_size;
    if (osz >= OUTN + ATTNN) { out_ext = dout; attn_ext = dout + OUTN; }
    else if (osz == ATTNN)   { attn_ext = dout; }
    else                     { out_ext = dout; }

    cudaFuncSetAttribute(fused_attn, cudaFuncAttributeMaxDynamicSharedMemorySize, FA_SMEM);

    dim3 t(256);
    mma_gemm<0><<<dim3(NQKV / 128, MTOT / 128), t>>>(x, w_qkv, b_qkv, nullptr);
    fused_attn<<<dim3(S_ / 128, BHN), t, FA_SMEM>>>(attn_ext);
    mma_gemm<3><<<dim3(D_ / 128, MTOT / 128), t>>>(nullptr, w_out, b_out, out_ext);
}